// round 9
// baseline (speedup 1.0000x reference)
#include <cuda_runtime.h>

#define SCALE   0.0625f
#define CC      64
#define HH      200
#define WW      304
#define NROI    512
#define CCHUNK  8
// T intermediate (after y-reduce): [c][i][x]; TXS=40 cols, plane stride 284
// (284*4 = 1136 ≡ 112 mod 128 -> 8 channel planes land on distinct line phases)
#define TXS     40
#define TPS     284
#define T_ELEMS (CCHUNK * TPS)     // 2272 floats ~ 9.1 KB

__device__ __forceinline__ int iclamp(int v, int lo, int hi) {
    return v < lo ? lo : (v > hi ? hi : v);
}

__global__ void __launch_bounds__(512, 4)
prroi_kernel(const float* __restrict__ feat,
             const float* __restrict__ rois,
             float* __restrict__ out)
{
    __shared__ float Tbuf[T_ELEMS];   // [c][i][x]
    __shared__ float wys[49];         // y weights, pre-scaled by 1/win
    __shared__ float wxs[49];         // x weights
    __shared__ int   gyr[49];         // absolute clamped row index * WW
    __shared__ int   gxs[49];         // clamped col index rel x0a (0..39)

    const int n  = blockIdx.y;
    const int c0 = blockIdx.x * CCHUNK;
    const int t  = threadIdx.x;

    const float* roi = rois + n * 5;
    const int   bi = (int)roi[0];
    const float sx = roi[1] * SCALE, sy = roi[2] * SCALE;
    const float ex = roi[3] * SCALE, ey = roi[4] * SCALE;
    const float ly = fmaxf(ey - sy, 0.f), lx = fmaxf(ex - sx, 0.f);
    const float by = ly * (1.f / 7.f), bx = lx * (1.f / 7.f);

    const int xlo = iclamp((int)floorf(sx), 0, WW - 1);
    const int xhi = iclamp((int)floorf(sx + bx * 6.f) + 6, 0, WW - 1);
    const int x0a = xlo & ~3;

    // ---- weights: threads 0..6 -> y axis p, 7..13 -> x axis p ----
    if (t < 14) {
        const bool isx   = t >= 7;
        const int  p     = isx ? t - 7 : t;
        const float start = isx ? sx : sy;
        const float bin   = isx ? bx : by;
        const int   size  = isx ? WW : HH;

        // fold 1/win into the y weights; win<=0 -> scale 0 -> output 0
        const float win  = bx * by;
        const float wscl = isx ? 1.f : ((win > 0.f) ? 1.f / fmaxf(win, 1e-12f) : 0.f);

        float ws = start + bin * (float)p;
        float we = ws + bin;
        float s  = floorf(ws);
        float Lk[6], Rk[6];
#pragma unroll
        for (int k = 0; k < 6; k++) {
            float cell = s + (float)k;
            bool  act  = cell < we;
            float X0 = fmaxf(ws, cell), X1 = fminf(we, cell + 1.f);
            float a0 = X0 - cell, a1 = X1 - cell;
            Lk[k] = act ? (a1 - 0.5f * a1 * a1 - a0 + 0.5f * a0 * a0) : 0.f;
            float b1v = cell + 1.f - X0, b0v = cell + 1.f - X1;
            Rk[k] = act ? (b1v - 0.5f * b1v * b1v - b0v + 0.5f * b0v * b0v) : 0.f;
        }
        int si = (int)s;
        float* wdst = isx ? wxs : wys;
        int*   gdst = isx ? gxs : gyr;
#pragma unroll
        for (int k = 0; k < 7; k++) {
            float w = (k < 6 ? Lk[k] : 0.f) + (k > 0 ? Rk[k - 1] : 0.f);
            int idx = si + k;
            if (idx < 0 || idx >= size) w = 0.f;
            int ic = iclamp(idx, 0, size - 1);
            wdst[p * 7 + k] = w * wscl;
            gdst[p * 7 + k] = isx ? (ic - x0a) : ic * WW;   // x: rel idx; y: row offset
        }
    }

    __syncthreads();

    // ---- fused pass 1: y-reduce straight from global memory.
    //      warp = item (c, i); lanes sweep x (scalar, coalesced 128B lines).
    {
        const int w = t >> 5, l = t & 31;
        const int  xA = x0a + l;
        const bool aA = (xA <= xhi);                    // xhi <= WW-1: no OOB
        const int  xB = xA + 32;
        const bool aB = (l < 8) && (xB <= xhi);

        for (int id = w; id < CCHUNK * 7; id += 16) {
            const int c = id / 7;                       // constant divisor
            const int i = id - 7 * c;
            const float* bp = feat + ((size_t)bi * CC + c0 + c) * (size_t)(HH * WW);

            float wyv[7];
            int   ro[7];
#pragma unroll
            for (int a = 0; a < 7; a++) {
                wyv[a] = wys[i * 7 + a];
                ro[a]  = gyr[i * 7 + a];                // absolute row * WW
            }
            float acc0 = 0.f, acc1 = 0.f;
#pragma unroll
            for (int a = 0; a < 7; a++) {
                const float* rp = bp + ro[a];
                if (aA) acc0 += wyv[a] * rp[xA];
                if (aB) acc1 += wyv[a] * rp[xB];
            }
            float* Tp = Tbuf + c * TPS + i * TXS;
            if (aA) Tp[l]      = acc0;
            if (aB) Tp[32 + l] = acc1;
        }
    }

    __syncthreads();

    // ---- pass 2: x-reduce, mapped (c = t/49, ij = t%49) -> coalesced STG ----
    if (t < CCHUNK * 49) {
        const int c  = t / 49;
        const int ij = t - 49 * c;
        const int i  = ij / 7;
        const int j  = ij - 7 * i;
        const float* Tp = Tbuf + c * TPS + i * TXS;
        float wxv[7];
        int   cb[7];
#pragma unroll
        for (int b = 0; b < 7; b++) {
            wxv[b] = wxs[j * 7 + b];
            cb[b]  = gxs[j * 7 + b];
        }
        float acc = 0.f;
#pragma unroll
        for (int b = 0; b < 7; b++)
            acc += wxv[b] * Tp[cb[b]];
        out[((size_t)n * CC + c0) * 49 + t] = acc;      // wy pre-scaled by 1/win
    }
}

extern "C" void kernel_launch(void* const* d_in, const int* in_sizes, int n_in,
                              void* d_out, int out_size)
{
    const float* feat = (const float*)d_in[0];
    const float* rois = (const float*)d_in[1];
    float* out = (float*)d_out;

    prroi_kernel<<<dim3(CC / CCHUNK, NROI), 512>>>(feat, rois, out);
}

// round 11
// speedup vs baseline: 1.1310x; 1.1310x over previous
#include <cuda_runtime.h>

#define SCALE   0.0625f
#define CC      64
#define HH      200
#define WW      304
#define NROI    512
#define CCHUNK  8
// T intermediate (after y-reduce): [c][i][x]; TXS=40 cols, plane stride 284
#define TXS     40
#define TPS     284
#define T_ELEMS (CCHUNK * TPS)     // 2272 floats ~ 9.1 KB

__device__ __forceinline__ int iclamp(int v, int lo, int hi) {
    return v < lo ? lo : (v > hi ? hi : v);
}

__global__ void __launch_bounds__(512, 4)
prroi_kernel(const float* __restrict__ feat,
             const float* __restrict__ rois,
             float* __restrict__ out)
{
    __shared__ float Tbuf[T_ELEMS];   // [c][i][x]
    __shared__ float wys[49];         // y weights, pre-scaled by 1/win
    __shared__ float wxs[49];         // x weights
    __shared__ int   gyr[49];         // absolute clamped row index * WW
    __shared__ int   gxs[49];         // clamped col index rel x0a (0..39)

    const int n  = blockIdx.y;
    const int c0 = blockIdx.x * CCHUNK;
    const int t  = threadIdx.x;

    const float* roi = rois + n * 5;
    const int   bi = (int)roi[0];
    const float sx = roi[1] * SCALE, sy = roi[2] * SCALE;
    const float ex = roi[3] * SCALE, ey = roi[4] * SCALE;
    const float ly = fmaxf(ey - sy, 0.f), lx = fmaxf(ex - sx, 0.f);
    const float by = ly * (1.f / 7.f), bx = lx * (1.f / 7.f);

    const int xlo = iclamp((int)floorf(sx), 0, WW - 1);
    const int xhi = iclamp((int)floorf(sx + bx * 6.f) + 6, 0, WW - 1);
    const int x0a = xlo & ~3;

    // ---- weights: threads 0..6 -> y axis p, 7..13 -> x axis p ----
    if (t < 14) {
        const bool isx   = t >= 7;
        const int  p     = isx ? t - 7 : t;
        const float start = isx ? sx : sy;
        const float bin   = isx ? bx : by;
        const int   size  = isx ? WW : HH;

        // fold 1/win into the y weights; win<=0 -> scale 0 -> output 0
        const float win  = bx * by;
        const float wscl = isx ? 1.f : ((win > 0.f) ? 1.f / fmaxf(win, 1e-12f) : 0.f);

        float ws = start + bin * (float)p;
        float we = ws + bin;
        float s  = floorf(ws);
        float Lk[6], Rk[6];
#pragma unroll
        for (int k = 0; k < 6; k++) {
            float cell = s + (float)k;
            bool  act  = cell < we;
            float X0 = fmaxf(ws, cell), X1 = fminf(we, cell + 1.f);
            float a0 = X0 - cell, a1 = X1 - cell;
            Lk[k] = act ? (a1 - 0.5f * a1 * a1 - a0 + 0.5f * a0 * a0) : 0.f;
            float b1v = cell + 1.f - X0, b0v = cell + 1.f - X1;
            Rk[k] = act ? (b1v - 0.5f * b1v * b1v - b0v + 0.5f * b0v * b0v) : 0.f;
        }
        int si = (int)s;
        float* wdst = isx ? wxs : wys;
        int*   gdst = isx ? gxs : gyr;
#pragma unroll
        for (int k = 0; k < 7; k++) {
            float w = (k < 6 ? Lk[k] : 0.f) + (k > 0 ? Rk[k - 1] : 0.f);
            int idx = si + k;
            if (idx < 0 || idx >= size) w = 0.f;
            int ic = iclamp(idx, 0, size - 1);
            wdst[p * 7 + k] = w * wscl;
            gdst[p * 7 + k] = isx ? (ic - x0a) : ic * WW;   // x: rel idx; y: row offset
        }
    }

    __syncthreads();

    // ---- fused pass 1: y-reduce straight from global memory, float2-wide.
    //      warp = (c = w>>1, i = w&1, w&1+2, ...); lanes 0..19 cover 40 cols.
    {
        const int w = t >> 5, l = t & 31;
        const int c = w >> 1;
        const int x2 = x0a + 2 * l;
        const bool act = (l < 20) && (x2 <= xhi);
        const float* bpx = feat + ((size_t)bi * CC + c0 + c) * (size_t)(HH * WW) + x2;
        float* Tc = Tbuf + c * TPS + 2 * l;

#pragma unroll
        for (int i = (w & 1); i < 7; i += 2) {
            float wyv[7];
            int   ro[7];
#pragma unroll
            for (int a = 0; a < 7; a++) {
                wyv[a] = wys[i * 7 + a];
                ro[a]  = gyr[i * 7 + a];                // absolute row * WW
            }
            if (act) {
                float a0 = 0.f, a1 = 0.f;
#pragma unroll
                for (int a = 0; a < 7; a++) {
                    const float2 v = *reinterpret_cast<const float2*>(bpx + ro[a]);
                    a0 += wyv[a] * v.x;
                    a1 += wyv[a] * v.y;
                }
                float2 r; r.x = a0; r.y = a1;
                *reinterpret_cast<float2*>(Tc + i * TXS) = r;
            }
        }
    }

    __syncthreads();

    // ---- pass 2: x-reduce, mapped (c = t/49, ij = t%49) -> coalesced STG ----
    if (t < CCHUNK * 49) {
        const int c  = t / 49;
        const int ij = t - 49 * c;
        const int i  = ij / 7;
        const int j  = ij - 7 * i;
        const float* Tp = Tbuf + c * TPS + i * TXS;
        float wxv[7];
        int   cb[7];
#pragma unroll
        for (int b = 0; b < 7; b++) {
            wxv[b] = wxs[j * 7 + b];
            cb[b]  = gxs[j * 7 + b];
        }
        float acc = 0.f;
#pragma unroll
        for (int b = 0; b < 7; b++)
            acc += wxv[b] * Tp[cb[b]];
        out[((size_t)n * CC + c0) * 49 + t] = acc;      // wy pre-scaled by 1/win
    }
}

extern "C" void kernel_launch(void* const* d_in, const int* in_sizes, int n_in,
                              void* d_out, int out_size)
{
    const float* feat = (const float*)d_in[0];
    const float* rois = (const float*)d_in[1];
    float* out = (float*)d_out;

    prroi_kernel<<<dim3(CC / CCHUNK, NROI), 512>>>(feat, rois, out);
}

// round 15
// speedup vs baseline: 1.1822x; 1.0453x over previous
#include <cuda_runtime.h>

#define SCALE   0.0625f
#define CC      64
#define HH      200
#define WW      304
#define NROI    512
#define CCHUNK  8
// T intermediate (after y-reduce): [c][i][x]; TXS=40 cols, plane stride 284
#define TXS     40
#define TPS     284
#define T_ELEMS (CCHUNK * TPS)     // 2272 floats ~ 9.1 KB

__device__ __forceinline__ int iclamp(int v, int lo, int hi) {
    return v < lo ? lo : (v > hi ? hi : v);
}

__global__ void __launch_bounds__(512, 4)
prroi_kernel(const float* __restrict__ feat,
             const float* __restrict__ rois,
             float* __restrict__ out)
{
    __shared__ float Tbuf[T_ELEMS];               // [c][i][x]
    __shared__ __align__(16) float wys2[56];      // [i][8] y weights (1/win folded)
    __shared__ __align__(16) float wxs2[56];      // [j][8] x weights
    __shared__ __align__(16) int   gyr2[56];      // [i][8] row*WW; slot 7 = fast flag
    __shared__ __align__(16) int   gxs2[56];      // [j][8] col rel x0a

    const int n  = blockIdx.y;
    const int c0 = blockIdx.x * CCHUNK;
    const int t  = threadIdx.x;

    const float* roi = rois + n * 5;
    const int   bi = (int)roi[0];
    const float sx = roi[1] * SCALE, sy = roi[2] * SCALE;
    const float ex = roi[3] * SCALE, ey = roi[4] * SCALE;
    const float ly = fmaxf(ey - sy, 0.f), lx = fmaxf(ex - sx, 0.f);
    const float by = ly * (1.f / 7.f), bx = lx * (1.f / 7.f);

    const int xlo = iclamp((int)floorf(sx), 0, WW - 1);
    const int xhi = iclamp((int)floorf(sx + bx * 6.f) + 6, 0, WW - 1);
    const int x0a = xlo & ~3;

    // ---- weights: threads 0..6 -> y axis p, 7..13 -> x axis p ----
    if (t < 14) {
        const bool isx   = t >= 7;
        const int  p     = isx ? t - 7 : t;
        const float start = isx ? sx : sy;
        const float bin   = isx ? bx : by;
        const int   size  = isx ? WW : HH;

        // fold 1/win into the y weights; win<=0 -> scale 0 -> output 0
        const float win  = bx * by;
        const float wscl = isx ? 1.f : ((win > 0.f) ? 1.f / fmaxf(win, 1e-12f) : 0.f);

        float ws = start + bin * (float)p;
        float we = ws + bin;
        float s  = floorf(ws);
        float Lk[6], Rk[6];
#pragma unroll
        for (int k = 0; k < 6; k++) {
            float cell = s + (float)k;
            bool  act  = cell < we;
            float X0 = fmaxf(ws, cell), X1 = fminf(we, cell + 1.f);
            float a0 = X0 - cell, a1 = X1 - cell;
            Lk[k] = act ? (a1 - 0.5f * a1 * a1 - a0 + 0.5f * a0 * a0) : 0.f;
            float b1v = cell + 1.f - X0, b0v = cell + 1.f - X1;
            Rk[k] = act ? (b1v - 0.5f * b1v * b1v - b0v + 0.5f * b0v * b0v) : 0.f;
        }
        int si = (int)s;
        float* wdst = isx ? wxs2 : wys2;
        int*   gdst = isx ? gxs2 : gyr2;
#pragma unroll
        for (int k = 0; k < 7; k++) {
            float w = (k < 6 ? Lk[k] : 0.f) + (k > 0 ? Rk[k - 1] : 0.f);
            int idx = si + k;
            if (idx < 0 || idx >= size) w = 0.f;
            int ic = iclamp(idx, 0, size - 1);
            wdst[p * 8 + k] = w * wscl;
            gdst[p * 8 + k] = isx ? (ic - x0a) : ic * WW;   // x: rel idx; y: row offset
        }
        // y-bin fast flag: taps si..si+6 all in range -> consecutive rows
        if (!isx) gdst[p * 8 + 7] = (si >= 0 && si + 6 < HH) ? 1 : 0;
    }

    __syncthreads();

    // ---- fused pass 1: y-reduce straight from global memory, float2-wide.
    //      warp = (c = w>>1, i = w&1, +2); lanes 0..19 cover 40 cols. ----
    {
        const int w = t >> 5, l = t & 31;
        const int c = w >> 1;
        const int x2 = x0a + 2 * l;
        const bool act = (l < 20) && (x2 <= xhi);   // x2 even, x2+1 <= 303: in-bounds
        const float* bpx = feat + ((size_t)bi * CC + c0 + c) * (size_t)(HH * WW) + x2;
        float* Tc = Tbuf + c * TPS + 2 * l;

        for (int i = (w & 1); i < 7; i += 2) {
            if (act) {
                const float4 wlo = *reinterpret_cast<const float4*>(wys2 + i * 8);
                const float4 whi = *reinterpret_cast<const float4*>(wys2 + i * 8 + 4);
                const int4   rlo = *reinterpret_cast<const int4*>(gyr2 + i * 8);
                const int4   rhi = *reinterpret_cast<const int4*>(gyr2 + i * 8 + 4);
                float a0, a1;
                if (rhi.w) {                       // fast: 7 consecutive rows,
                    const float* p = bpx + rlo.x;  // immediate-offset loads
                    float2 v0 = *reinterpret_cast<const float2*>(p);
                    float2 v1 = *reinterpret_cast<const float2*>(p + WW);
                    float2 v2 = *reinterpret_cast<const float2*>(p + 2 * WW);
                    float2 v3 = *reinterpret_cast<const float2*>(p + 3 * WW);
                    float2 v4 = *reinterpret_cast<const float2*>(p + 4 * WW);
                    float2 v5 = *reinterpret_cast<const float2*>(p + 5 * WW);
                    float2 v6 = *reinterpret_cast<const float2*>(p + 6 * WW);
                    a0 = wlo.x*v0.x + wlo.y*v1.x + wlo.z*v2.x + wlo.w*v3.x
                       + whi.x*v4.x + whi.y*v5.x + whi.z*v6.x;
                    a1 = wlo.x*v0.y + wlo.y*v1.y + wlo.z*v2.y + wlo.w*v3.y
                       + whi.x*v4.y + whi.y*v5.y + whi.z*v6.y;
                } else {                           // generic: clamped rows
                    float2 v0 = *reinterpret_cast<const float2*>(bpx + rlo.x);
                    float2 v1 = *reinterpret_cast<const float2*>(bpx + rlo.y);
                    float2 v2 = *reinterpret_cast<const float2*>(bpx + rlo.z);
                    float2 v3 = *reinterpret_cast<const float2*>(bpx + rlo.w);
                    float2 v4 = *reinterpret_cast<const float2*>(bpx + rhi.x);
                    float2 v5 = *reinterpret_cast<const float2*>(bpx + rhi.y);
                    float2 v6 = *reinterpret_cast<const float2*>(bpx + rhi.z);
                    a0 = wlo.x*v0.x + wlo.y*v1.x + wlo.z*v2.x + wlo.w*v3.x
                       + whi.x*v4.x + whi.y*v5.x + whi.z*v6.x;
                    a1 = wlo.x*v0.y + wlo.y*v1.y + wlo.z*v2.y + wlo.w*v3.y
                       + whi.x*v4.y + whi.y*v5.y + whi.z*v6.y;
                }
                float2 r; r.x = a0; r.y = a1;
                *reinterpret_cast<float2*>(Tc + i * TXS) = r;
            }
        }
    }

    __syncthreads();

    // ---- pass 2: x-reduce, mapped (c = t/49, ij = t%49) -> coalesced STG ----
    if (t < CCHUNK * 49) {
        const int c  = t / 49;
        const int ij = t - 49 * c;
        const int i  = ij / 7;
        const int j  = ij - 7 * i;
        const float* Tp = Tbuf + c * TPS + i * TXS;
        const float4 wlo = *reinterpret_cast<const float4*>(wxs2 + j * 8);
        const float4 whi = *reinterpret_cast<const float4*>(wxs2 + j * 8 + 4);
        const int4   clo = *reinterpret_cast<const int4*>(gxs2 + j * 8);
        const int4   chi = *reinterpret_cast<const int4*>(gxs2 + j * 8 + 4);
        float acc = wlo.x * Tp[clo.x] + wlo.y * Tp[clo.y]
                  + wlo.z * Tp[clo.z] + wlo.w * Tp[clo.w]
                  + whi.x * Tp[chi.x] + whi.y * Tp[chi.y]
                  + whi.z * Tp[chi.z];
        out[((size_t)n * CC + c0) * 49 + t] = acc;      // wy pre-scaled by 1/win
    }
}

extern "C" void kernel_launch(void* const* d_in, const int* in_sizes, int n_in,
                              void* d_out, int out_size)
{
    const float* feat = (const float*)d_in[0];
    const float* rois = (const float*)d_in[1];
    float* out = (float*)d_out;

    prroi_kernel<<<dim3(CC / CCHUNK, NROI), 512>>>(feat, rois, out);
}

// round 16
// speedup vs baseline: 1.2455x; 1.0535x over previous
#include <cuda_runtime.h>

#define SCALE   0.0625f
#define CC      64
#define HH      200
#define WW      304
#define NROI    512
#define CCHUNK  16
// T intermediate (after y-reduce): [c][i][x]; TXS=40 cols, plane stride 284
#define TXS     40
#define TPS     284
#define T_ELEMS (CCHUNK * TPS)     // 4544 floats ~ 18.2 KB

__device__ __forceinline__ int iclamp(int v, int lo, int hi) {
    return v < lo ? lo : (v > hi ? hi : v);
}

__global__ void __launch_bounds__(512, 4)
prroi_kernel(const float* __restrict__ feat,
             const float* __restrict__ rois,
             float* __restrict__ out)
{
    __shared__ float Tbuf[T_ELEMS];               // [c][i][x]
    __shared__ __align__(16) float wys2[56];      // [i][8] y weights (1/win folded)
    __shared__ __align__(16) float wxs2[56];      // [j][8] x weights
    __shared__ __align__(16) int   gyr2[56];      // [i][8] row*WW; slot 7 = fast flag
    __shared__ __align__(16) int   gxs2[56];      // [j][8] col rel x0a

    const int n  = blockIdx.y;
    const int c0 = blockIdx.x * CCHUNK;
    const int t  = threadIdx.x;

    const float* roi = rois + n * 5;
    const int   bi = (int)roi[0];
    const float sx = roi[1] * SCALE, sy = roi[2] * SCALE;
    const float ex = roi[3] * SCALE, ey = roi[4] * SCALE;
    const float ly = fmaxf(ey - sy, 0.f), lx = fmaxf(ex - sx, 0.f);
    const float by = ly * (1.f / 7.f), bx = lx * (1.f / 7.f);

    const int xlo = iclamp((int)floorf(sx), 0, WW - 1);
    const int xhi = iclamp((int)floorf(sx + bx * 6.f) + 6, 0, WW - 1);
    const int x0a = xlo & ~3;

    // ---- weights: threads 0..6 -> y axis p, 7..13 -> x axis p ----
    if (t < 14) {
        const bool isx   = t >= 7;
        const int  p     = isx ? t - 7 : t;
        const float start = isx ? sx : sy;
        const float bin   = isx ? bx : by;
        const int   size  = isx ? WW : HH;

        // fold 1/win into the y weights; win<=0 -> scale 0 -> output 0
        const float win  = bx * by;
        const float wscl = isx ? 1.f : ((win > 0.f) ? 1.f / fmaxf(win, 1e-12f) : 0.f);

        float ws = start + bin * (float)p;
        float we = ws + bin;
        float s  = floorf(ws);
        float Lk[6], Rk[6];
#pragma unroll
        for (int k = 0; k < 6; k++) {
            float cell = s + (float)k;
            bool  act  = cell < we;
            float X0 = fmaxf(ws, cell), X1 = fminf(we, cell + 1.f);
            float a0 = X0 - cell, a1 = X1 - cell;
            Lk[k] = act ? (a1 - 0.5f * a1 * a1 - a0 + 0.5f * a0 * a0) : 0.f;
            float b1v = cell + 1.f - X0, b0v = cell + 1.f - X1;
            Rk[k] = act ? (b1v - 0.5f * b1v * b1v - b0v + 0.5f * b0v * b0v) : 0.f;
        }
        int si = (int)s;
        float* wdst = isx ? wxs2 : wys2;
        int*   gdst = isx ? gxs2 : gyr2;
#pragma unroll
        for (int k = 0; k < 7; k++) {
            float w = (k < 6 ? Lk[k] : 0.f) + (k > 0 ? Rk[k - 1] : 0.f);
            int idx = si + k;
            if (idx < 0 || idx >= size) w = 0.f;
            int ic = iclamp(idx, 0, size - 1);
            wdst[p * 8 + k] = w * wscl;
            gdst[p * 8 + k] = isx ? (ic - x0a) : ic * WW;   // x: rel idx; y: row offset
        }
        // y-bin fast flag: taps si..si+6 all in range -> consecutive rows
        if (!isx) gdst[p * 8 + 7] = (si >= 0 && si + 6 < HH) ? 1 : 0;
    }

    __syncthreads();

    // ---- fused pass 1: y-reduce straight from global memory, float2-wide.
    //      warp = one channel (16 warps = 16 channels); lanes 0..19 cover 40 cols;
    //      i-loop fully unrolled -> ptxas hoists loads across iterations. ----
    {
        const int w = t >> 5, l = t & 31;
        const int x2 = x0a + 2 * l;
        const bool act = (l < 20) && (x2 <= xhi);   // x2 even, x2+1 <= 303: in-bounds
        const float* bpx = feat + ((size_t)bi * CC + c0 + w) * (size_t)(HH * WW) + x2;
        float* Tc = Tbuf + w * TPS + 2 * l;

        if (act) {
#pragma unroll
            for (int i = 0; i < 7; i++) {
                const float4 wlo = *reinterpret_cast<const float4*>(wys2 + i * 8);
                const float4 whi = *reinterpret_cast<const float4*>(wys2 + i * 8 + 4);
                const int4   rlo = *reinterpret_cast<const int4*>(gyr2 + i * 8);
                const int4   rhi = *reinterpret_cast<const int4*>(gyr2 + i * 8 + 4);
                float a0, a1;
                if (rhi.w) {                       // fast: 7 consecutive rows,
                    const float* p = bpx + rlo.x;  // immediate-offset loads
                    float2 v0 = *reinterpret_cast<const float2*>(p);
                    float2 v1 = *reinterpret_cast<const float2*>(p + WW);
                    float2 v2 = *reinterpret_cast<const float2*>(p + 2 * WW);
                    float2 v3 = *reinterpret_cast<const float2*>(p + 3 * WW);
                    float2 v4 = *reinterpret_cast<const float2*>(p + 4 * WW);
                    float2 v5 = *reinterpret_cast<const float2*>(p + 5 * WW);
                    float2 v6 = *reinterpret_cast<const float2*>(p + 6 * WW);
                    a0 = wlo.x*v0.x + wlo.y*v1.x + wlo.z*v2.x + wlo.w*v3.x
                       + whi.x*v4.x + whi.y*v5.x + whi.z*v6.x;
                    a1 = wlo.x*v0.y + wlo.y*v1.y + wlo.z*v2.y + wlo.w*v3.y
                       + whi.x*v4.y + whi.y*v5.y + whi.z*v6.y;
                } else {                           // generic: clamped rows
                    float2 v0 = *reinterpret_cast<const float2*>(bpx + rlo.x);
                    float2 v1 = *reinterpret_cast<const float2*>(bpx + rlo.y);
                    float2 v2 = *reinterpret_cast<const float2*>(bpx + rlo.z);
                    float2 v3 = *reinterpret_cast<const float2*>(bpx + rlo.w);
                    float2 v4 = *reinterpret_cast<const float2*>(bpx + rhi.x);
                    float2 v5 = *reinterpret_cast<const float2*>(bpx + rhi.y);
                    float2 v6 = *reinterpret_cast<const float2*>(bpx + rhi.z);
                    a0 = wlo.x*v0.x + wlo.y*v1.x + wlo.z*v2.x + wlo.w*v3.x
                       + whi.x*v4.x + whi.y*v5.x + whi.z*v6.x;
                    a1 = wlo.x*v0.y + wlo.y*v1.y + wlo.z*v2.y + wlo.w*v3.y
                       + whi.x*v4.y + whi.y*v5.y + whi.z*v6.y;
                }
                float2 r; r.x = a0; r.y = a1;
                *reinterpret_cast<float2*>(Tc + i * TXS) = r;
            }
        }
    }

    __syncthreads();

    // ---- pass 2: x-reduce. o = t, t+512 covers 16*49 = 784 outputs;
    //      consecutive o -> coalesced STG. ----
#pragma unroll
    for (int o = t; o < CCHUNK * 49; o += 512) {
        const int c  = o / 49;
        const int ij = o - 49 * c;
        const int i  = ij / 7;
        const int j  = ij - 7 * i;
        const float* Tp = Tbuf + c * TPS + i * TXS;
        const float4 wlo = *reinterpret_cast<const float4*>(wxs2 + j * 8);
        const float4 whi = *reinterpret_cast<const float4*>(wxs2 + j * 8 + 4);
        const int4   clo = *reinterpret_cast<const int4*>(gxs2 + j * 8);
        const int4   chi = *reinterpret_cast<const int4*>(gxs2 + j * 8 + 4);
        float acc = wlo.x * Tp[clo.x] + wlo.y * Tp[clo.y]
                  + wlo.z * Tp[clo.z] + wlo.w * Tp[clo.w]
                  + whi.x * Tp[chi.x] + whi.y * Tp[chi.y]
                  + whi.z * Tp[chi.z];
        out[((size_t)n * CC + c0) * 49 + o] = acc;      // wy pre-scaled by 1/win
    }
}

extern "C" void kernel_launch(void* const* d_in, const int* in_sizes, int n_in,
                              void* d_out, int out_size)
{
    const float* feat = (const float*)d_in[0];
    const float* rois = (const float*)d_in[1];
    float* out = (float*)d_out;

    prroi_kernel<<<dim3(CC / CCHUNK, NROI), 512>>>(feat, rois, out);
}